// round 16
// baseline (speedup 1.0000x reference)
#include <cuda_runtime.h>
#include <cstdint>

// Fixed shapes from reference setup_inputs
#define BATCH   2
#define N_IN    524288                       // 64*64*128
#define N_POOL  131072                       // 32*32*128
#define N_OUT   32

// Output layout (floats): [w_zero 33554432] [b_u_ 64] [w_zero 33554432] [b_l_ 64]
#define OFF_BU    33554432LL
#define OFF_WZ2   33554496LL
#define OFF_BL    67108928LL

// Region0 (bytes [0, 134217728)) -> zeroed by the parallel memset branch.
// Region1 (bytes [134217984, 268435712)) -> zeroed by in-kernel TMA stores.
#define R0_BYTES      134217728LL
#define R1_START      (OFF_WZ2 * 4LL)        // 134217984, 16B-aligned
#define REGION_BYTES  134217728LL            // region1 size

// 592 blocks = 4 CTAs/SM on 148 SMs (one wave) — measured optimum.
#define NBLK        592
#define BLK_PER_B   296
#define R_THREADS   256
#define P_PER_BLK   443                      // ceil(131072/296)
#define ZB_PER_BLK  226720LL                 // ceil(REGION_BYTES/592) to 16B
#define BUF_BYTES   49152                    // 48 KiB static SMEM zero source

// Cross-block reduction scratch (zero-initialized; reset by last block each run)
__device__ float        g_pu[BATCH][N_OUT];
__device__ float        g_pl[BATCH][N_OUT];
__device__ unsigned int g_cnt[BATCH];

// ---------------------------------------------------------------------------
// Hybrid kernel: TMA bulk-zeroes its slice of REGION1 (fire-and-forget, issued
// before the read loop) + read-only maxpool/weight-fold reduction + last-block
// bias epilogue. Runs CONCURRENTLY with the memset branch zeroing REGION0 —
// two independent write engines on disjoint halves of the output.
// ---------------------------------------------------------------------------
__global__ __launch_bounds__(R_THREADS, 4)
void fused_kernel(const float* __restrict__ u,
                  const float* __restrict__ l,
                  const float4* __restrict__ wu,
                  const float4* __restrict__ wl,
                  const float* __restrict__ bias_u,
                  const float* __restrict__ bias_l,
                  float* __restrict__ out) {
    const int bid = blockIdx.x;
    const int tid = threadIdx.x;

    __shared__ float4 zbuf[BUF_BYTES / 16];     // 48 KiB of zeros
    __shared__ float  s_u[N_OUT];
    __shared__ float  s_l[N_OUT];
    __shared__ int    s_last;

    // ---- 1) zero the SMEM source buffer ------------------------------------
    const float4 zv = make_float4(0.f, 0.f, 0.f, 0.f);
    #pragma unroll
    for (int i = tid; i < BUF_BYTES / 16; i += R_THREADS) zbuf[i] = zv;
    if (tid < N_OUT) { s_u[tid] = 0.0f; s_l[tid] = 0.0f; }
    __syncthreads();

    const int b     = (bid >= BLK_PER_B) ? 1 : 0;
    const int chunk = bid - b * BLK_PER_B;

    // ---- 2) fire-and-forget TMA zero stores over REGION1 slice -------------
    if (tid == 0) {
        asm volatile("fence.proxy.async.shared::cta;" ::: "memory");
        uint32_t saddr;
        asm("{ .reg .u64 t; cvta.to.shared.u64 t, %1; cvt.u32.u64 %0, t; }"
            : "=r"(saddr) : "l"(zbuf));
        char* gbase = (char*)out + R1_START;
        long long g0 = (long long)bid * ZB_PER_BLK;
        long long g1 = g0 + ZB_PER_BLK;
        if (g1 > REGION_BYTES) g1 = REGION_BYTES;
        for (long long g = g0; g < g1; g += BUF_BYTES) {
            uint32_t sz = (uint32_t)((g1 - g) < BUF_BYTES ? (g1 - g) : BUF_BYTES);
            asm volatile(
                "cp.async.bulk.global.shared::cta.bulk_group [%0], [%1], %2;"
                :: "l"(gbase + g), "r"(saddr), "r"(sz) : "memory");
        }
        asm volatile("cp.async.bulk.commit_group;" ::: "memory");
    }

    // ---- 3) read-only reduce (overlaps TMA drain + memset branch) ----------
    const int o4  = tid & 7;          // which float4 of the 32-wide N_OUT row
    const int pof = tid >> 3;         // 0..31

    const int p_begin = chunk * P_PER_BLK;
    const int p_end   = min(p_begin + P_PER_BLK, N_POOL);

    const long long wbase = (long long)b * N_POOL;
    const float* ub = u + (long long)b * N_IN;
    const float* lb = l + (long long)b * N_IN;

    float4 au = make_float4(0.f, 0.f, 0.f, 0.f);
    float4 al = make_float4(0.f, 0.f, 0.f, 0.f);

    for (int p = p_begin + pof; p < p_end; p += 32) {
        // inline 2x2 stride-2 NHWC maxpool
        int c  = p & 127;
        int pw = (p >> 7) & 31;
        int ph = p >> 12;
        int base = (ph << 14) + (pw << 8) + c;   // 2*ph*64*128 + 2*pw*128 + c
        float bu = fmaxf(fmaxf(__ldg(ub + base),        __ldg(ub + base + 128)),
                         fmaxf(__ldg(ub + base + 8192), __ldg(ub + base + 8320)));
        float bl = fmaxf(fmaxf(__ldg(lb + base),        __ldg(lb + base + 128)),
                         fmaxf(__ldg(lb + base + 8192), __ldg(lb + base + 8320)));

        long long row = (wbase + p) * 8 + o4;
        float4 wuv = __ldcs(wu + row);
        float4 wlv = __ldcs(wl + row);

        au.x = fmaf(fmaxf(wuv.x, 0.f), bu, fmaf(fminf(wuv.x, 0.f), bl, au.x));
        au.y = fmaf(fmaxf(wuv.y, 0.f), bu, fmaf(fminf(wuv.y, 0.f), bl, au.y));
        au.z = fmaf(fmaxf(wuv.z, 0.f), bu, fmaf(fminf(wuv.z, 0.f), bl, au.z));
        au.w = fmaf(fmaxf(wuv.w, 0.f), bu, fmaf(fminf(wuv.w, 0.f), bl, au.w));

        al.x = fmaf(fmaxf(wlv.x, 0.f), bl, fmaf(fminf(wlv.x, 0.f), bu, al.x));
        al.y = fmaf(fmaxf(wlv.y, 0.f), bl, fmaf(fminf(wlv.y, 0.f), bu, al.y));
        al.z = fmaf(fmaxf(wlv.z, 0.f), bl, fmaf(fminf(wlv.z, 0.f), bu, al.z));
        al.w = fmaf(fmaxf(wlv.w, 0.f), bl, fmaf(fminf(wlv.w, 0.f), bu, al.w));
    }

    // ---- 4) block partials -> global scratch; last block writes output -----
    int ob = o4 * 4;
    atomicAdd(&s_u[ob + 0], au.x);
    atomicAdd(&s_u[ob + 1], au.y);
    atomicAdd(&s_u[ob + 2], au.z);
    atomicAdd(&s_u[ob + 3], au.w);
    atomicAdd(&s_l[ob + 0], al.x);
    atomicAdd(&s_l[ob + 1], al.y);
    atomicAdd(&s_l[ob + 2], al.z);
    atomicAdd(&s_l[ob + 3], al.w);
    __syncthreads();

    if (tid < N_OUT) {
        atomicAdd(&g_pu[b][tid], s_u[tid]);
        atomicAdd(&g_pl[b][tid], s_l[tid]);
    }
    __threadfence();
    if (tid == 0) {
        unsigned t = atomicAdd(&g_cnt[b], 1u);
        s_last = (t == BLK_PER_B - 1u) ? 1 : 0;
    }
    __syncthreads();

    if (s_last) {
        if (tid < N_OUT) {
            float su = g_pu[b][tid];
            float sl = g_pl[b][tid];
            out[OFF_BU + b * N_OUT + tid] = su + __ldg(bias_u + b * N_OUT + tid);
            out[OFF_BL + b * N_OUT + tid] = sl + __ldg(bias_l + b * N_OUT + tid);
            // reset scratch for the next graph replay
            g_pu[b][tid] = 0.0f;
            g_pl[b][tid] = 0.0f;
        }
        __syncthreads();
        if (tid == 0) {
            __threadfence();
            g_cnt[b] = 0u;
        }
    }

    // ---- 5) drain TMA stores before SMEM goes away (tid0 holds CTA alive) --
    if (tid == 0) {
        asm volatile("cp.async.bulk.wait_group 0;" ::: "memory");
    }
}

// ---------------------------------------------------------------------------
// kernel_launch: fork the capture stream. Side branch memsets REGION0 while
// the fused kernel TMA-zeroes REGION1 and does the reduction. Join at the end.
// ---------------------------------------------------------------------------
extern "C" void kernel_launch(void* const* d_in, const int* in_sizes, int n_in,
                              void* d_out, int out_size) {
    // Input order: y, x_0, u_c, l_c, w_out_u, b_out_u, w_out_l, b_out_l
    const float* u_c     = (const float*)d_in[2];
    const float* l_c     = (const float*)d_in[3];
    const float* w_out_u = (const float*)d_in[4];
    const float* b_out_u = (const float*)d_in[5];
    const float* w_out_l = (const float*)d_in[6];
    const float* b_out_l = (const float*)d_in[7];
    float* out = (float*)d_out;

    static cudaStream_t side = nullptr;
    static cudaEvent_t  evFork = nullptr, evJoin = nullptr;
    if (side == nullptr) {
        cudaStreamCreateWithFlags(&side, cudaStreamNonBlocking);
        cudaEventCreateWithFlags(&evFork, cudaEventDisableTiming);
        cudaEventCreateWithFlags(&evJoin, cudaEventDisableTiming);
    }

    // Fork: side stream branches off the capture stream.
    cudaEventRecord(evFork, 0);
    cudaStreamWaitEvent(side, evFork, 0);

    // Branch A (side): zero REGION0 via the driver fill path.
    cudaMemsetAsync((char*)out, 0, (size_t)R0_BYTES, side);
    cudaEventRecord(evJoin, side);

    // Branch B (main): TMA-zero REGION1 + reduce + bias epilogue.
    fused_kernel<<<NBLK, R_THREADS>>>(u_c, l_c,
                                      (const float4*)w_out_u,
                                      (const float4*)w_out_l,
                                      b_out_u, b_out_l, out);

    // Join: main stream completes only after both branches.
    cudaStreamWaitEvent(0, evJoin, 0);
}